// round 16
// baseline (speedup 1.0000x reference)
#include <cuda_runtime.h>
#include <cuda_fp16.h>
#include <math.h>
#include <stdint.h>

// Shapes (fixed by the problem)
#define NB   16
#define CCH  256
#define HH   32
#define WW   32
#define LL   (HH*WW)       // 1024
#define PP   2048
#define KEEP 102           // int(0.05 * 2048)
#define K3   768           // 3x fp16 split K (h | l*64 | h/64) . (h | h/64 | l*64)

// ---------------------------------------------------------------------------
// Scratch (device globals only; no allocations allowed)
// ---------------------------------------------------------------------------
__device__ float  g_invxn[NB * LL];                    // 64 KB
__device__ __half g_A[(size_t)NB * LL * K3];           // 25 MB  A' split of x^T * invxn
__device__ __half g_B[(size_t)PP * K3];                // 3 MB   B' split of poolN
__device__ __half g_pool16[PP * CCH];                  // 1 MB   fp16 copy of raw pool (gather)
__device__ float  g_cos[(size_t)NB * LL * PP];         // 134 MB

// ---------------------------------------------------------------------------
// Kernel 1: normalize pool rows -> fp16 split B'; also write fp16 pool copy.
// ---------------------------------------------------------------------------
__global__ void prep_pool(const float* __restrict__ pool) {
    int p = blockIdx.x;
    int c = threadIdx.x;
    float v = pool[p * CCH + c];
    g_pool16[p * CCH + c] = __float2half(v);
    __shared__ float red[256];
    red[c] = v * v;
    __syncthreads();
    #pragma unroll
    for (int s = 128; s > 0; s >>= 1) {
        if (c < s) red[c] += red[c + s];
        __syncthreads();
    }
    float vn = v * (1.0f / sqrtf(red[0]));
    __half h  = __float2half(vn);
    float  hf = __half2float(h);
    __half l  = __float2half((vn - hf) * 64.0f);     // scaled residual (normal range)
    __half hs = __float2half(hf * 0.015625f);        // h / 64 (exact pow2 scale)
    __half* dst = g_B + (size_t)p * K3 + c;
    dst[0]   = h;
    dst[256] = hs;
    dst[512] = l;
}

// ---------------------------------------------------------------------------
// Kernel 2: per-pixel inverse norm of x.
// ---------------------------------------------------------------------------
__global__ void prep_xnorm(const float* __restrict__ x) {
    int idx = blockIdx.x * 256 + threadIdx.x;   // 0 .. 16383
    int n = idx >> 10, l = idx & (LL - 1);
    const float* xp = x + (size_t)n * CCH * LL + l;
    float s = 0.f;
    #pragma unroll 8
    for (int c = 0; c < CCH; c++) {
        float v = xp[c * LL];
        s = fmaf(v, v, s);
    }
    g_invxn[idx] = 1.0f / sqrtf(s);
}

// ---------------------------------------------------------------------------
// Kernel 3: transpose x [n][c][l] -> A' [n][l][K3] fp16 split [h | l*64 | h/64],
// with invxn folded in. 32x32 tiles, 256 threads.
// ---------------------------------------------------------------------------
__global__ __launch_bounds__(256) void prep_xT(const float* __restrict__ x) {
    int n  = blockIdx.z;
    int c0 = blockIdx.y * 32;
    int l0 = blockIdx.x * 32;
    int tx = threadIdx.x & 31;
    int ty = threadIdx.x >> 5;     // 0..7
    __shared__ float ss[32][33];

    const float* xp = x + (size_t)n * CCH * LL;
    #pragma unroll
    for (int i = 0; i < 4; i++) {
        int c = ty * 4 + i;
        ss[c][tx] = xp[(size_t)(c0 + c) * LL + l0 + tx];
    }
    __syncthreads();
    #pragma unroll
    for (int i = 0; i < 4; i++) {
        int lloc = ty * 4 + i;
        float s = g_invxn[n * LL + l0 + lloc];
        float v = ss[tx][lloc] * s;
        __half h  = __float2half(v);
        float  hf = __half2float(h);
        __half l  = __float2half((v - hf) * 64.0f);
        __half hs = __float2half(hf * 0.015625f);
        __half* dst = g_A + ((size_t)(n * LL + l0 + lloc)) * K3 + c0 + tx;
        dst[0]   = h;
        dst[256] = l;
        dst[512] = hs;
    }
}

// ---------------------------------------------------------------------------
// Kernel 4: HMMA GEMM, CTA tile 128(l) x 256(p), 512 threads, 16 warps in
// 4x4 (warp tile 32x64), BK=64, 3-stage cp.async pipeline, stride 144 B.
// R15 analysis: 128x128 tiles moved 768 MB through L2 (=the kernel time);
// 128x256 cuts operand traffic to 576 MB (-25%). Same warps/SM (16).
// ---------------------------------------------------------------------------
#define GBK    64
#define NCHUNK (K3 / GBK)          // 12
#define ASTRB  144                 // smem row stride in bytes (72 halves)
#define ASTAGE (128 * ASTRB)       // 18432
#define BSTAGE (256 * ASTRB)       // 36864
#define STGSZ  (ASTAGE + BSTAGE)   // 55296
#define SM_A_OFF(s) ((s) * STGSZ)
#define SM_B_OFF(s) ((s) * STGSZ + ASTAGE)
#define SMEM_GEMM  (3 * STGSZ)     // 165888 (3 stages)

__device__ __forceinline__ uint32_t smem_u32(const void* p) {
    uint32_t a;
    asm("{ .reg .u64 t; cvta.to.shared.u64 t, %1; cvt.u32.u64 %0, t; }" : "=r"(a) : "l"(p));
    return a;
}
#define CP16(sm_addr, gptr) \
    asm volatile("cp.async.cg.shared.global [%0], [%1], 16;" :: "r"(sm_addr), "l"(gptr) : "memory")
#define CP_COMMIT() asm volatile("cp.async.commit_group;" ::: "memory")
#define CP_WAIT(N)  asm volatile("cp.async.wait_group %0;" :: "n"(N) : "memory")

#define LDSM4(R0, R1, R2, R3, ADDR) \
    asm volatile("ldmatrix.sync.aligned.m8n8.x4.shared.b16 {%0,%1,%2,%3}, [%4];" \
        : "=r"(R0), "=r"(R1), "=r"(R2), "=r"(R3) : "r"(ADDR))

__device__ __forceinline__ void mma_fp16(float* c, const uint32_t* a,
                                         uint32_t b0, uint32_t b1) {
    asm volatile(
        "mma.sync.aligned.m16n8k16.row.col.f32.f16.f16.f32 "
        "{%0,%1,%2,%3}, {%4,%5,%6,%7}, {%8,%9}, {%0,%1,%2,%3};"
        : "+f"(c[0]), "+f"(c[1]), "+f"(c[2]), "+f"(c[3])
        : "r"(a[0]), "r"(a[1]), "r"(a[2]), "r"(a[3]), "r"(b0), "r"(b1));
}

__global__ __launch_bounds__(512, 1) void gemm_mma() {
    extern __shared__ __align__(1024) char sm[];
    uint32_t smb = smem_u32(sm);

    int tid  = threadIdx.x;
    int lane = tid & 31;
    int warp = tid >> 5;        // 0..15
    int wm   = warp & 3;        // 0..3  (M strip, 32 rows)
    int wn   = warp >> 2;       // 0..3  (N strip, 64 cols)

    int n    = blockIdx.z;
    int pBlk = blockIdx.x * 256;
    int lBlk = blockIdx.y * 128;

    const __half* Ag = g_A + ((size_t)(n * LL + lBlk)) * K3;
    const __half* Bg = g_B + (size_t)pBlk * K3;

    // Loaders: A = 128 rows x 8 segs = 1024 segs (2/thread);
    //          B = 256 rows x 8 segs = 2048 segs (4/thread).
    #define LOADCHUNK(KC, S)                                                     \
    {                                                                            \
        int kc_ = (KC);                                                          \
        uint32_t sa = smb + SM_A_OFF(S);                                         \
        uint32_t sb = smb + SM_B_OFF(S);                                         \
        _Pragma("unroll")                                                        \
        for (int j = 0; j < 2; j++) {                                            \
            int u = tid + j * 512;                                               \
            int row = u >> 3, seg = u & 7;                                       \
            CP16(sa + row * ASTRB + seg * 16,                                    \
                 Ag + (size_t)row * K3 + kc_ * GBK + seg * 8);                   \
        }                                                                        \
        _Pragma("unroll")                                                        \
        for (int j = 0; j < 4; j++) {                                            \
            int u = tid + j * 512;                                               \
            int row = u >> 3, seg = u & 7;                                       \
            CP16(sb + row * ASTRB + seg * 16,                                    \
                 Bg + (size_t)row * K3 + kc_ * GBK + seg * 8);                   \
        }                                                                        \
    }

    float acc[2][8][4];
    #pragma unroll
    for (int i = 0; i < 2; i++)
        #pragma unroll
        for (int j = 0; j < 8; j++)
            #pragma unroll
            for (int q = 0; q < 4; q++) acc[i][j][q] = 0.f;

    // ldmatrix lane-address decomposition (same structure as validated R12;
    // only the warp-tile strides changed: A mt in {0,1}, B nt2 in {0..3}).
    int lrow = lane & 7;
    int lm   = lane >> 3;   // 0..3
    uint32_t aOff = (uint32_t)((wm * 32 + (lm & 1) * 8 + lrow) * ASTRB + (lm >> 1) * 16);
    uint32_t bOff = (uint32_t)((wn * 64 + (lm >> 1) * 8 + lrow) * ASTRB + (lm & 1) * 16);

    LOADCHUNK(0, 0);
    CP_COMMIT();
    LOADCHUNK(1, 1);
    CP_COMMIT();

    int s = 0;
    #pragma unroll 1
    for (int kc = 0; kc < NCHUNK; kc++) {
        if (kc < NCHUNK - 1) { CP_WAIT(1); } else { CP_WAIT(0); }
        __syncthreads();
        if (kc + 2 < NCHUNK) {
            int s2 = s + 2; if (s2 >= 3) s2 -= 3;
            LOADCHUNK(kc + 2, s2);
            CP_COMMIT();
        }

        uint32_t sA = smb + SM_A_OFF(s) + aOff;
        uint32_t sB = smb + SM_B_OFF(s) + bOff;

        #pragma unroll
        for (int ks = 0; ks < GBK / 16; ks++) {
            uint32_t a[2][4], b[4][4];
            #pragma unroll
            for (int mt = 0; mt < 2; mt++)
                LDSM4(a[mt][0], a[mt][1], a[mt][2], a[mt][3],
                      sA + mt * (16 * ASTRB) + ks * 32);
            #pragma unroll
            for (int nt2 = 0; nt2 < 4; nt2++)
                LDSM4(b[nt2][0], b[nt2][1], b[nt2][2], b[nt2][3],
                      sB + nt2 * (16 * ASTRB) + ks * 32);
            #pragma unroll
            for (int mt = 0; mt < 2; mt++)
                #pragma unroll
                for (int nt = 0; nt < 8; nt++)
                    mma_fp16(acc[mt][nt], a[mt],
                             b[nt >> 1][(nt & 1) * 2], b[nt >> 1][(nt & 1) * 2 + 1]);
        }
        if (++s == 3) s = 0;
    }

    // Epilogue: write g_cos[n][l][p]
    int r  = lane >> 2;        // 0..7
    int cq = lane & 3;         // 0..3
    #pragma unroll
    for (int mt = 0; mt < 2; mt++) {
        int l0 = lBlk + wm * 32 + mt * 16 + r;
        float* row0 = g_cos + ((size_t)(n * LL + l0)) * PP + pBlk;
        float* row1 = g_cos + ((size_t)(n * LL + l0 + 8)) * PP + pBlk;
        #pragma unroll
        for (int nt = 0; nt < 8; nt++) {
            int p = wn * 64 + nt * 8 + cq * 2;
            float2 v0 = make_float2(acc[mt][nt][0], acc[mt][nt][1]);
            float2 v1 = make_float2(acc[mt][nt][2], acc[mt][nt][3]);
            *(float2*)&row0[p] = v0;
            *(float2*)&row1[p] = v1;
        }
    }
}

// ---------------------------------------------------------------------------
// Kernel 5: WARP-PER-PIXEL exact top-102 + sparse recon (R15-proven).
// New: gather uses a manual depth-4 software pipeline (wbuf/hbuf prefetch)
// to lift MLP from ~2 to 4+ — the dependent LDS->LDG->FMA chain was the
// remaining latency cost.
// ---------------------------------------------------------------------------
#define CAND_MAX 112
#define CAND_ARR 192
#define MAXIT    24

__global__ __launch_bounds__(256, 2) void topk_recon(const float* __restrict__ pool,
                                                     float* __restrict__ out) {
    int lane = threadIdx.x & 31;
    int warp = threadIdx.x >> 5;
    int pixel = blockIdx.x * 8 + warp;          // 0 .. 16383
    int n = pixel >> 10, l = pixel & (LL - 1);
    const float* row = g_cos + (size_t)pixel * PP;
    const float4* row4 = (const float4*)row;

    __shared__ float ckey[8][CAND_ARR];
    __shared__ int   cidx[8][CAND_ARR];
    __shared__ int   s_idx[8][KEEP];
    __shared__ float s_val[8][KEEP];
    __shared__ int   wcnt[8];

    // Load 64 keys per lane (coalesced float4: element idx = i*128+lane*4+c).
    float key[64];
    #pragma unroll
    for (int i = 0; i < 16; i++) {
        float4 v = __ldg(&row4[i * 32 + lane]);
        key[i * 4 + 0] = fabsf(v.x);
        key[i * 4 + 1] = fabsf(v.y);
        key[i * 4 + 2] = fabsf(v.z);
        key[i * 4 + 3] = fabsf(v.w);
    }
    if (lane == 0) wcnt[warp] = 0;
    __syncwarp();

    // Warp-local binary search. Invariant: count(key >= lo) >= KEEP.
    unsigned lo = 0u, hi = 0x3FC00000u;
    int cntLo = PP;
    int it = 0;
    while (cntLo > CAND_MAX && it < MAXIT) {
        unsigned mid = (lo + hi) >> 1;
        float mf = __uint_as_float(mid);
        int c = 0;
        #pragma unroll
        for (int k = 0; k < 64; k++) c += (key[k] >= mf);
        c = __reduce_add_sync(0xFFFFFFFFu, c);
        if (c >= KEEP) { lo = mid; cntLo = c; }
        else           { hi = mid; }
        it++;
    }
    float loF = __uint_as_float(lo);

    // Collect candidates into this warp's smem region.
    #pragma unroll
    for (int i = 0; i < 16; i++) {
        #pragma unroll
        for (int comp = 0; comp < 4; comp++) {
            float kv = key[i * 4 + comp];
            if (kv >= loF) {
                int slot = atomicAdd(&wcnt[warp], 1);
                if (slot < CAND_ARR) {
                    ckey[warp][slot] = kv;
                    cidx[warp][slot] = i * 128 + lane * 4 + comp;
                }
            }
        }
    }
    __syncwarp();
    int C = wcnt[warp];
    if (C > CAND_ARR) C = CAND_ARR;    // safety (unreachable with real data)

    // Exact rank per candidate (inner reads are LDS broadcasts).
    for (int i = lane; i < C; i += 32) {
        float ki = ckey[warp][i];
        int   ii = cidx[warp][i];
        int rank = 0;
        #pragma unroll 4
        for (int j = 0; j < C; j++) {
            float kj = ckey[warp][j];
            int   ij = cidx[warp][j];
            rank += (kj > ki) | ((kj == ki) & (ij < ii));
        }
        if (rank < KEEP) {
            s_idx[warp][rank] = ii;
            s_val[warp][rank] = __ldg(&row[ii]);   // signed value (L1/L2-hot)
        }
    }
    __syncwarp();

    // Deterministic rank-ordered sum (fixed-order shfl tree).
    float v = s_val[warp][lane] + s_val[warp][lane + 32] + s_val[warp][lane + 64]
            + ((lane + 96 < KEEP) ? s_val[warp][lane + 96] : 0.f);
    #pragma unroll
    for (int off = 16; off > 0; off >>= 1)
        v += __shfl_down_sync(0xFFFFFFFFu, v, off);
    float invS = 1.0f / __shfl_sync(0xFFFFFFFFu, v, 0);

    // Gather with depth-4 software pipeline: per keep-term the warp loads one
    // full fp16 pool row (512 B, uint4/lane); prefetch 4 terms ahead.
    float acc[8] = {0.f, 0.f, 0.f, 0.f, 0.f, 0.f, 0.f, 0.f};
    uint4 hbuf[4];
    float wbuf[4];
    #pragma unroll
    for (int t = 0; t < 4; t++) {
        wbuf[t] = s_val[warp][t];
        hbuf[t] = *(const uint4*)(g_pool16 + (size_t)s_idx[warp][t] * CCH + lane * 8);
    }
    #pragma unroll 2
    for (int j = 0; j < KEEP; j++) {
        uint4 h = hbuf[j & 3];
        float w = wbuf[j & 3];
        if (j + 4 < KEEP) {
            wbuf[j & 3] = s_val[warp][j + 4];
            hbuf[j & 3] = *(const uint4*)(g_pool16 + (size_t)s_idx[warp][j + 4] * CCH + lane * 8);
        }
        const __half2* hp = (const __half2*)&h;
        float2 f0 = __half22float2(hp[0]);
        float2 f1 = __half22float2(hp[1]);
        float2 f2 = __half22float2(hp[2]);
        float2 f3 = __half22float2(hp[3]);
        acc[0] = fmaf(w, f0.x, acc[0]);
        acc[1] = fmaf(w, f0.y, acc[1]);
        acc[2] = fmaf(w, f1.x, acc[2]);
        acc[3] = fmaf(w, f1.y, acc[3]);
        acc[4] = fmaf(w, f2.x, acc[4]);
        acc[5] = fmaf(w, f2.y, acc[5]);
        acc[6] = fmaf(w, f3.x, acc[6]);
        acc[7] = fmaf(w, f3.y, acc[7]);
    }

    float* outp = out + (size_t)n * CCH * LL + (size_t)(lane * 8) * LL + l;
    #pragma unroll
    for (int c8 = 0; c8 < 8; c8++)
        outp[(size_t)c8 * LL] = acc[c8] * invS;
}

// ---------------------------------------------------------------------------
// Launch
// ---------------------------------------------------------------------------
extern "C" void kernel_launch(void* const* d_in, const int* in_sizes, int n_in,
                              void* d_out, int out_size) {
    const float* x    = (const float*)d_in[0];  // [16, 256, 32, 32]
    const float* pool = (const float*)d_in[1];  // [2048, 256]
    float* out        = (float*)d_out;          // [16, 256, 32, 32]

    cudaFuncSetAttribute(gemm_mma, cudaFuncAttributeMaxDynamicSharedMemorySize, SMEM_GEMM);

    prep_pool<<<PP, 256>>>(pool);
    prep_xnorm<<<(NB * LL) / 256, 256>>>(x);
    prep_xT<<<dim3(LL / 32, CCH / 32, NB), 256>>>(x);
    gemm_mma<<<dim3(PP / 256, LL / 128, NB), 512, SMEM_GEMM>>>();
    topk_recon<<<NB * LL / 8, 256>>>(pool, out);
}

// round 17
// speedup vs baseline: 1.7121x; 1.7121x over previous
#include <cuda_runtime.h>
#include <cuda_fp16.h>
#include <math.h>
#include <stdint.h>

// Shapes (fixed by the problem)
#define NB   16
#define CCH  256
#define HH   32
#define WW   32
#define LL   (HH*WW)       // 1024
#define PP   2048
#define KEEP 102           // int(0.05 * 2048)
#define KPAD 104           // KEEP padded to multiple of 4 (pad weights = 0)
#define K3   768           // 3x fp16 split K (h | l*64 | h/64) . (h | h/64 | l*64)

// ---------------------------------------------------------------------------
// Scratch (device globals only; no allocations allowed)
// ---------------------------------------------------------------------------
__device__ float  g_invxn[NB * LL];                    // 64 KB
__device__ __half g_A[(size_t)NB * LL * K3];           // 25 MB  A' split of x^T * invxn
__device__ __half g_B[(size_t)PP * K3];                // 3 MB   B' split of poolN
__device__ __half g_pool16[PP * CCH];                  // 1 MB   fp16 copy of raw pool (gather)
__device__ float  g_cos[(size_t)NB * LL * PP];         // 134 MB

// ---------------------------------------------------------------------------
// Kernel 1: normalize pool rows -> fp16 split B'; also write fp16 pool copy.
// ---------------------------------------------------------------------------
__global__ void prep_pool(const float* __restrict__ pool) {
    int p = blockIdx.x;
    int c = threadIdx.x;
    float v = pool[p * CCH + c];
    g_pool16[p * CCH + c] = __float2half(v);
    __shared__ float red[256];
    red[c] = v * v;
    __syncthreads();
    #pragma unroll
    for (int s = 128; s > 0; s >>= 1) {
        if (c < s) red[c] += red[c + s];
        __syncthreads();
    }
    float vn = v * (1.0f / sqrtf(red[0]));
    __half h  = __float2half(vn);
    float  hf = __half2float(h);
    __half l  = __float2half((vn - hf) * 64.0f);     // scaled residual (normal range)
    __half hs = __float2half(hf * 0.015625f);        // h / 64 (exact pow2 scale)
    __half* dst = g_B + (size_t)p * K3 + c;
    dst[0]   = h;
    dst[256] = hs;
    dst[512] = l;
}

// ---------------------------------------------------------------------------
// Kernel 2: per-pixel inverse norm of x.
// ---------------------------------------------------------------------------
__global__ void prep_xnorm(const float* __restrict__ x) {
    int idx = blockIdx.x * 256 + threadIdx.x;   // 0 .. 16383
    int n = idx >> 10, l = idx & (LL - 1);
    const float* xp = x + (size_t)n * CCH * LL + l;
    float s = 0.f;
    #pragma unroll 8
    for (int c = 0; c < CCH; c++) {
        float v = xp[c * LL];
        s = fmaf(v, v, s);
    }
    g_invxn[idx] = 1.0f / sqrtf(s);
}

// ---------------------------------------------------------------------------
// Kernel 3: transpose x [n][c][l] -> A' [n][l][K3] fp16 split [h | l*64 | h/64],
// with invxn folded in. 32x32 tiles, 256 threads.
// ---------------------------------------------------------------------------
__global__ __launch_bounds__(256) void prep_xT(const float* __restrict__ x) {
    int n  = blockIdx.z;
    int c0 = blockIdx.y * 32;
    int l0 = blockIdx.x * 32;
    int tx = threadIdx.x & 31;
    int ty = threadIdx.x >> 5;     // 0..7
    __shared__ float ss[32][33];

    const float* xp = x + (size_t)n * CCH * LL;
    #pragma unroll
    for (int i = 0; i < 4; i++) {
        int c = ty * 4 + i;
        ss[c][tx] = xp[(size_t)(c0 + c) * LL + l0 + tx];
    }
    __syncthreads();
    #pragma unroll
    for (int i = 0; i < 4; i++) {
        int lloc = ty * 4 + i;
        float s = g_invxn[n * LL + l0 + lloc];
        float v = ss[tx][lloc] * s;
        __half h  = __float2half(v);
        float  hf = __half2float(h);
        __half l  = __float2half((v - hf) * 64.0f);
        __half hs = __float2half(hf * 0.015625f);
        __half* dst = g_A + ((size_t)(n * LL + l0 + lloc)) * K3 + c0 + tx;
        dst[0]   = h;
        dst[256] = l;
        dst[512] = hs;
    }
}

// ---------------------------------------------------------------------------
// Kernel 4: HMMA GEMM via mma.sync + ldmatrix, 3-stage cp.async pipeline.
// EXACT R15 revert: CTA 128x128, 8 warps 2x4, 256 thr, 2 CTA/SM (150.7us).
// R16 falsified the L2-BW theory (less traffic, lower L2%, slower) — this
// shape is the structural optimum for this toolchain path; do not grow tiles.
// ---------------------------------------------------------------------------
#define GBK    64
#define NCHUNK (K3 / GBK)          // 12
#define ASTRB  144                 // smem row stride in bytes (72 halves)
#define STAGE_BYTES (128 * ASTRB)  // 18432 per operand
#define SM_A_OFF(s) ((s) * 2 * STAGE_BYTES)
#define SM_B_OFF(s) ((s) * 2 * STAGE_BYTES + STAGE_BYTES)
#define SMEM_GEMM  (6 * STAGE_BYTES)   // 110592 (3 stages)

__device__ __forceinline__ uint32_t smem_u32(const void* p) {
    uint32_t a;
    asm("{ .reg .u64 t; cvta.to.shared.u64 t, %1; cvt.u32.u64 %0, t; }" : "=r"(a) : "l"(p));
    return a;
}
#define CP16(sm_addr, gptr) \
    asm volatile("cp.async.cg.shared.global [%0], [%1], 16;" :: "r"(sm_addr), "l"(gptr) : "memory")
#define CP_COMMIT() asm volatile("cp.async.commit_group;" ::: "memory")
#define CP_WAIT(N)  asm volatile("cp.async.wait_group %0;" :: "n"(N) : "memory")

#define LDSM4(R0, R1, R2, R3, ADDR) \
    asm volatile("ldmatrix.sync.aligned.m8n8.x4.shared.b16 {%0,%1,%2,%3}, [%4];" \
        : "=r"(R0), "=r"(R1), "=r"(R2), "=r"(R3) : "r"(ADDR))

__device__ __forceinline__ void mma_fp16(float* c, const uint32_t* a,
                                         uint32_t b0, uint32_t b1) {
    asm volatile(
        "mma.sync.aligned.m16n8k16.row.col.f32.f16.f16.f32 "
        "{%0,%1,%2,%3}, {%4,%5,%6,%7}, {%8,%9}, {%0,%1,%2,%3};"
        : "+f"(c[0]), "+f"(c[1]), "+f"(c[2]), "+f"(c[3])
        : "r"(a[0]), "r"(a[1]), "r"(a[2]), "r"(a[3]), "r"(b0), "r"(b1));
}

__global__ __launch_bounds__(256, 2) void gemm_mma() {
    extern __shared__ __align__(1024) char sm[];
    uint32_t smb = smem_u32(sm);

    int tid  = threadIdx.x;
    int lane = tid & 31;
    int warp = tid >> 5;
    int wm   = warp & 1;        // 0..1  (M half, 64 rows)
    int wn   = warp >> 1;       // 0..3  (N quarter, 32 cols)

    int n    = blockIdx.z;
    int pBlk = blockIdx.x * 128;
    int lBlk = blockIdx.y * 128;

    const __half* Ag = g_A + ((size_t)(n * LL + lBlk)) * K3;
    const __half* Bg = g_B + (size_t)pBlk * K3;

    #define LOADCHUNK(KC, S)                                                     \
    {                                                                            \
        int kc_ = (KC);                                                          \
        uint32_t sa = smb + SM_A_OFF(S);                                         \
        uint32_t sb = smb + SM_B_OFF(S);                                         \
        _Pragma("unroll")                                                        \
        for (int j = 0; j < 4; j++) {                                            \
            int u = tid + j * 256;                                               \
            int row = u >> 3, seg = u & 7;                                       \
            CP16(sa + row * ASTRB + seg * 16,                                    \
                 Ag + (size_t)row * K3 + kc_ * GBK + seg * 8);                   \
        }                                                                        \
        _Pragma("unroll")                                                        \
        for (int j = 0; j < 4; j++) {                                            \
            int u = tid + j * 256;                                               \
            int row = u >> 3, seg = u & 7;                                       \
            CP16(sb + row * ASTRB + seg * 16,                                    \
                 Bg + (size_t)row * K3 + kc_ * GBK + seg * 8);                   \
        }                                                                        \
    }

    float acc[4][4][4];
    #pragma unroll
    for (int i = 0; i < 4; i++)
        #pragma unroll
        for (int j = 0; j < 4; j++)
            #pragma unroll
            for (int q = 0; q < 4; q++) acc[i][j][q] = 0.f;

    // ldmatrix lane-address decomposition (validated in R12).
    int lrow = lane & 7;
    int lm   = lane >> 3;   // 0..3
    uint32_t aOff = (uint32_t)((wm * 64 + (lm & 1) * 8 + lrow) * ASTRB + (lm >> 1) * 16);
    uint32_t bOff = (uint32_t)((wn * 32 + (lm >> 1) * 8 + lrow) * ASTRB + (lm & 1) * 16);

    LOADCHUNK(0, 0);
    CP_COMMIT();
    LOADCHUNK(1, 1);
    CP_COMMIT();

    int s = 0;
    #pragma unroll 1
    for (int kc = 0; kc < NCHUNK; kc++) {
        if (kc < NCHUNK - 1) { CP_WAIT(1); } else { CP_WAIT(0); }
        __syncthreads();
        if (kc + 2 < NCHUNK) {
            int s2 = s + 2; if (s2 >= 3) s2 -= 3;
            LOADCHUNK(kc + 2, s2);
            CP_COMMIT();
        }

        uint32_t sA = smb + SM_A_OFF(s) + aOff;
        uint32_t sB = smb + SM_B_OFF(s) + bOff;

        #pragma unroll
        for (int ks = 0; ks < GBK / 16; ks++) {
            uint32_t a[4][4], b[2][4];
            #pragma unroll
            for (int mt = 0; mt < 4; mt++)
                LDSM4(a[mt][0], a[mt][1], a[mt][2], a[mt][3],
                      sA + mt * (16 * ASTRB) + ks * 32);
            #pragma unroll
            for (int nt2 = 0; nt2 < 2; nt2++)
                LDSM4(b[nt2][0], b[nt2][1], b[nt2][2], b[nt2][3],
                      sB + nt2 * (16 * ASTRB) + ks * 32);
            #pragma unroll
            for (int mt = 0; mt < 4; mt++)
                #pragma unroll
                for (int nt = 0; nt < 4; nt++)
                    mma_fp16(acc[mt][nt], a[mt],
                             b[nt >> 1][(nt & 1) * 2], b[nt >> 1][(nt & 1) * 2 + 1]);
        }
        if (++s == 3) s = 0;
    }

    // Epilogue: write g_cos[n][l][p]
    int r  = lane >> 2;        // 0..7
    int cq = lane & 3;         // 0..3
    #pragma unroll
    for (int mt = 0; mt < 4; mt++) {
        int l0 = lBlk + wm * 64 + mt * 16 + r;
        float* row0 = g_cos + ((size_t)(n * LL + l0)) * PP + pBlk;
        float* row1 = g_cos + ((size_t)(n * LL + l0 + 8)) * PP + pBlk;
        #pragma unroll
        for (int nt = 0; nt < 4; nt++) {
            int p = wn * 32 + nt * 8 + cq * 2;
            float2 v0 = make_float2(acc[mt][nt][0], acc[mt][nt][1]);
            float2 v1 = make_float2(acc[mt][nt][2], acc[mt][nt][3]);
            *(float2*)&row0[p] = v0;
            *(float2*)&row1[p] = v1;
        }
    }
}

// ---------------------------------------------------------------------------
// Kernel 5: WARP-PER-PIXEL exact top-102 + sparse recon.
// R16 lesson: dynamically-indexed prefetch buffers spill to local memory.
// This version pipelines with EXPLICIT named registers (h0..h3 / w0..w3,
// static indices only) over KEEP padded to 104 (pad weights = 0, idx = 0).
// ---------------------------------------------------------------------------
#define CAND_MAX 112
#define CAND_ARR 192
#define MAXIT    24

__global__ __launch_bounds__(256, 2) void topk_recon(const float* __restrict__ pool,
                                                     float* __restrict__ out) {
    int lane = threadIdx.x & 31;
    int warp = threadIdx.x >> 5;
    int pixel = blockIdx.x * 8 + warp;          // 0 .. 16383
    int n = pixel >> 10, l = pixel & (LL - 1);
    const float* row = g_cos + (size_t)pixel * PP;
    const float4* row4 = (const float4*)row;

    __shared__ float ckey[8][CAND_ARR];
    __shared__ int   cidx[8][CAND_ARR];
    __shared__ int   s_idx[8][KPAD];
    __shared__ float s_val[8][KPAD];
    __shared__ int   wcnt[8];

    // Load 64 keys per lane (coalesced float4: element idx = i*128+lane*4+c).
    float key[64];
    #pragma unroll
    for (int i = 0; i < 16; i++) {
        float4 v = __ldg(&row4[i * 32 + lane]);
        key[i * 4 + 0] = fabsf(v.x);
        key[i * 4 + 1] = fabsf(v.y);
        key[i * 4 + 2] = fabsf(v.z);
        key[i * 4 + 3] = fabsf(v.w);
    }
    if (lane == 0) wcnt[warp] = 0;
    // Zero the pad slots (weights 0 => no contribution; idx 0 is a valid row).
    if (lane < KPAD - KEEP) {
        s_val[warp][KEEP + lane] = 0.f;
        s_idx[warp][KEEP + lane] = 0;
    }
    __syncwarp();

    // Warp-local binary search. Invariant: count(key >= lo) >= KEEP.
    unsigned lo = 0u, hi = 0x3FC00000u;
    int cntLo = PP;
    int it = 0;
    while (cntLo > CAND_MAX && it < MAXIT) {
        unsigned mid = (lo + hi) >> 1;
        float mf = __uint_as_float(mid);
        int c = 0;
        #pragma unroll
        for (int k = 0; k < 64; k++) c += (key[k] >= mf);
        c = __reduce_add_sync(0xFFFFFFFFu, c);
        if (c >= KEEP) { lo = mid; cntLo = c; }
        else           { hi = mid; }
        it++;
    }
    float loF = __uint_as_float(lo);

    // Collect candidates into this warp's smem region.
    #pragma unroll
    for (int i = 0; i < 16; i++) {
        #pragma unroll
        for (int comp = 0; comp < 4; comp++) {
            float kv = key[i * 4 + comp];
            if (kv >= loF) {
                int slot = atomicAdd(&wcnt[warp], 1);
                if (slot < CAND_ARR) {
                    ckey[warp][slot] = kv;
                    cidx[warp][slot] = i * 128 + lane * 4 + comp;
                }
            }
        }
    }
    __syncwarp();
    int C = wcnt[warp];
    if (C > CAND_ARR) C = CAND_ARR;    // safety (unreachable with real data)

    // Exact rank per candidate (inner reads are LDS broadcasts).
    for (int i = lane; i < C; i += 32) {
        float ki = ckey[warp][i];
        int   ii = cidx[warp][i];
        int rank = 0;
        #pragma unroll 4
        for (int j = 0; j < C; j++) {
            float kj = ckey[warp][j];
            int   ij = cidx[warp][j];
            rank += (kj > ki) | ((kj == ki) & (ij < ii));
        }
        if (rank < KEEP) {
            s_idx[warp][rank] = ii;
            s_val[warp][rank] = __ldg(&row[ii]);   // signed value (L1/L2-hot)
        }
    }
    __syncwarp();

    // Deterministic rank-ordered sum (fixed-order shfl tree; pads are 0).
    float v = s_val[warp][lane] + s_val[warp][lane + 32] + s_val[warp][lane + 64]
            + ((lane + 96 < KEEP) ? s_val[warp][lane + 96] : 0.f);
    #pragma unroll
    for (int off = 16; off > 0; off >>= 1)
        v += __shfl_down_sync(0xFFFFFFFFu, v, off);
    float invS = 1.0f / __shfl_sync(0xFFFFFFFFu, v, 0);

    // Gather, depth-4 prefetch with EXPLICIT registers (no dynamic array
    // indexing -> no local-mem spill). 26 chunks of 4 over KPAD=104 terms.
    float acc[8] = {0.f, 0.f, 0.f, 0.f, 0.f, 0.f, 0.f, 0.f};
    const __half* pg = g_pool16;
    uint4 h0, h1, h2, h3;
    float w0, w1, w2, w3;
    w0 = s_val[warp][0]; h0 = *(const uint4*)(pg + (size_t)s_idx[warp][0] * CCH + lane * 8);
    w1 = s_val[warp][1]; h1 = *(const uint4*)(pg + (size_t)s_idx[warp][1] * CCH + lane * 8);
    w2 = s_val[warp][2]; h2 = *(const uint4*)(pg + (size_t)s_idx[warp][2] * CCH + lane * 8);
    w3 = s_val[warp][3]; h3 = *(const uint4*)(pg + (size_t)s_idx[warp][3] * CCH + lane * 8);

    #define FMA8(HV, WV)                                                    \
    {                                                                       \
        const __half2* hp_ = (const __half2*)&(HV);                         \
        float2 f0_ = __half22float2(hp_[0]);                                \
        float2 f1_ = __half22float2(hp_[1]);                                \
        float2 f2_ = __half22float2(hp_[2]);                                \
        float2 f3_ = __half22float2(hp_[3]);                                \
        acc[0] = fmaf((WV), f0_.x, acc[0]);                                 \
        acc[1] = fmaf((WV), f0_.y, acc[1]);                                 \
        acc[2] = fmaf((WV), f1_.x, acc[2]);                                 \
        acc[3] = fmaf((WV), f1_.y, acc[3]);                                 \
        acc[4] = fmaf((WV), f2_.x, acc[4]);                                 \
        acc[5] = fmaf((WV), f2_.y, acc[5]);                                 \
        acc[6] = fmaf((WV), f3_.x, acc[6]);                                 \
        acc[7] = fmaf((WV), f3_.y, acc[7]);                                 \
    }

    #pragma unroll 1
    for (int j0 = 0; j0 < KPAD - 4; j0 += 4) {
        uint4 c0 = h0, c1 = h1, c2 = h2, c3 = h3;
        float v0 = w0, v1 = w1, v2 = w2, v3 = w3;
        w0 = s_val[warp][j0 + 4]; h0 = *(const uint4*)(pg + (size_t)s_idx[warp][j0 + 4] * CCH + lane * 8);
        w1 = s_val[warp][j0 + 5]; h1 = *(const uint4*)(pg + (size_t)s_idx[warp][j0 + 5] * CCH + lane * 8);
        w2 = s_val[warp][j0 + 6]; h2 = *(const uint4*)(pg + (size_t)s_idx[warp][j0 + 6] * CCH + lane * 8);
        w3 = s_val[warp][j0 + 7]; h3 = *(const uint4*)(pg + (size_t)s_idx[warp][j0 + 7] * CCH + lane * 8);
        FMA8(c0, v0)
        FMA8(c1, v1)
        FMA8(c2, v2)
        FMA8(c3, v3)
    }
    FMA8(h0, w0)
    FMA8(h1, w1)
    FMA8(h2, w2)
    FMA8(h3, w3)
    #undef FMA8

    float* outp = out + (size_t)n * CCH * LL + (size_t)(lane * 8) * LL + l;
    #pragma unroll
    for (int c8 = 0; c8 < 8; c8++)
        outp[(size_t)c8 * LL] = acc[c8] * invS;
}

// ---------------------------------------------------------------------------
// Launch
// ---------------------------------------------------------------------------
extern "C" void kernel_launch(void* const* d_in, const int* in_sizes, int n_in,
                              void* d_out, int out_size) {
    const float* x    = (const float*)d_in[0];  // [16, 256, 32, 32]
    const float* pool = (const float*)d_in[1];  // [2048, 256]
    float* out        = (float*)d_out;          // [16, 256, 32, 32]

    cudaFuncSetAttribute(gemm_mma, cudaFuncAttributeMaxDynamicSharedMemorySize, SMEM_GEMM);

    prep_pool<<<PP, 256>>>(pool);
    prep_xnorm<<<(NB * LL) / 256, 256>>>(x);
    prep_xT<<<dim3(LL / 32, CCH / 32, NB), 256>>>(x);
    gemm_mma<<<dim3(PP / 128, LL / 128, NB), 256, SMEM_GEMM>>>();
    topk_recon<<<NB * LL / 8, 256>>>(pool, out);
}